// round 6
// baseline (speedup 1.0000x reference)
#include <cuda_runtime.h>
#include <math.h>

#define K  32
#define B  16384
#define DA 128
#define SPLITS 16   // CTAs per residue; CTA = (residue, split), 8 warps = 8 b-rows

// Fine-grained fused kernel (2048 CTAs self-balance) with prefetch-before-
// softmax AND occupancy pinned to 4 CTAs/SM (regs <= 64).
//
// Reshape-trick index: x_sum[b,d] = sum_k nt[k,b,d] * w[k, (b&127)*128 + d];
// all b with residue r = b&127 share one 128-column softmax (smem, per CTA).
//
// nt (256 MB, single-use, 2x L2) -> __ldcs evict-first; outputs -> __stcs.
// Softmax is two-pass (running max, reload ne from L2 for exp) to keep the
// 8 prefetched float4s resident without spilling.

__global__ void __launch_bounds__(256, 4) fused_all(
    const float* __restrict__ ne,   // [K, B]
    const float* __restrict__ nt,   // [K, B, DA]
    const float* __restrict__ np,   // [DA]
    const float* __restrict__ ew,   // [DA]
    const float* __restrict__ eb,   // [1]
    const float* __restrict__ tw,   // [DA]
    const float* __restrict__ tb,   // [DA]
    float* __restrict__ out)        // [B + B*DA]
{
    const int r = blockIdx.x & 127;      // residue
    const int s = blockIdx.x >> 7;       // split in [0, SPLITS)
    const int t = threadIdx.x;
    const int warp = t >> 5;
    const int lane = t & 31;
    const int b = r + 128 * (s * 8 + warp);

    __shared__ float wsm[K][DA];         // 16 KB softmax weights for this residue

    const size_t kstride4 = (size_t)B * DA / 4;   // float4 stride between k-slices
    const float4* nt4 = reinterpret_cast<const float4*>(nt + (size_t)b * DA) + lane;
    const float4* w4  = reinterpret_cast<const float4*>(&wsm[0][0]) + lane;  // + k*32

    // ---- prefetch batch 0 (k = 0..7) BEFORE softmax: HBM busy immediately ----
    float4 a[8];
#pragma unroll
    for (int j = 0; j < 8; j++)
        a[j] = __ldcs(nt4 + (size_t)j * kstride4);

    // ---- two-pass softmax: threads 0..127 each own one column (reg-lean) ----
    if (t < DA) {
        const float* nec = ne + r * DA + t;
        float m = -1e30f;
#pragma unroll
        for (int k = 0; k < K; k++)
            m = fmaxf(m, __ldg(nec + k * B));
        float ssum = 0.0f;
#pragma unroll
        for (int k = 0; k < K; k++) {
            const float e = __expf(__ldg(nec + k * B) - m);   // L2 hit on reload
            wsm[k][t] = e;
            ssum += e;
        }
        const float inv = __frcp_rn(ssum);
#pragma unroll
        for (int k = 0; k < K; k++)
            wsm[k][t] *= inv;
    }
    __syncthreads();

    // ---- streaming accumulation: batch 0 from prefetch, then k0 = 8,16,24 ----
    float4 acc = make_float4(0.f, 0.f, 0.f, 0.f);

#pragma unroll
    for (int j = 0; j < 8; j++) {
        const float4 w = w4[j * 32];                 // conflict-free LDS.128
        acc.x = fmaf(a[j].x, w.x, acc.x);
        acc.y = fmaf(a[j].y, w.y, acc.y);
        acc.z = fmaf(a[j].z, w.z, acc.z);
        acc.w = fmaf(a[j].w, w.w, acc.w);
    }

#pragma unroll
    for (int k0 = 8; k0 < K; k0 += 8) {
#pragma unroll
        for (int j = 0; j < 8; j++)
            a[j] = __ldcs(nt4 + (size_t)(k0 + j) * kstride4);
#pragma unroll
        for (int j = 0; j < 8; j++) {
            const float4 w = w4[(k0 + j) * 32];
            acc.x = fmaf(a[j].x, w.x, acc.x);
            acc.y = fmaf(a[j].y, w.y, acc.y);
            acc.z = fmaf(a[j].z, w.z, acc.z);
            acc.w = fmaf(a[j].w, w.w, acc.w);
        }
    }

    // ---- epilogue ----
    const float4 npv = __ldg(reinterpret_cast<const float4*>(np) + lane);
    float4 x_;
    x_.x = npv.x * acc.x;
    x_.y = npv.y * acc.y;
    x_.z = npv.z * acc.z;
    x_.w = npv.w * acc.w;

    const float4 ewv = __ldg(reinterpret_cast<const float4*>(ew) + lane);
    float dot = x_.x * ewv.x + x_.y * ewv.y + x_.z * ewv.z + x_.w * ewv.w;
#pragma unroll
    for (int off = 16; off > 0; off >>= 1)
        dot += __shfl_xor_sync(0xFFFFFFFFu, dot, off);

    const float effect = __frcp_rn(1.0f + __expf(-(dot + __ldg(eb))));

    if (lane == 0) __stcs(out + b, effect);

    const float4 twv = __ldg(reinterpret_cast<const float4*>(tw) + lane);
    const float4 tbv = __ldg(reinterpret_cast<const float4*>(tb) + lane);
    float4 res;
    res.x = effect * fmaf(twv.x, x_.x, tbv.x);
    res.y = effect * fmaf(twv.y, x_.y, tbv.y);
    res.z = effect * fmaf(twv.z, x_.z, tbv.z);
    res.w = effect * fmaf(twv.w, x_.w, tbv.w);

    __stcs(reinterpret_cast<float4*>(out + B + (size_t)b * DA) + lane, res);
}

extern "C" void kernel_launch(void* const* d_in, const int* in_sizes, int n_in,
                              void* d_out, int out_size) {
    // metadata order: x, neigh_effect, neigh_transform, n_param, ew, eb, tw, tb
    const float* ne = (const float*)d_in[1];
    const float* nt = (const float*)d_in[2];
    const float* np = (const float*)d_in[3];
    const float* ew = (const float*)d_in[4];
    const float* eb = (const float*)d_in[5];
    const float* tw = (const float*)d_in[6];
    const float* tb = (const float*)d_in[7];
    float* out = (float*)d_out;

    // 128 residues x 16 splits = 2048 CTAs; 8 warps/CTA -> one b-row per warp
    fused_all<<<128 * SPLITS, 256>>>(ne, nt, np, ew, eb, tw, tb, out);
}

// round 7
// speedup vs baseline: 1.1000x; 1.1000x over previous
#include <cuda_runtime.h>
#include <math.h>

#define K  32
#define B  16384
#define DA 128
#define SPLITS 32   // CTAs per residue; CTA = (residue, split), 4 warps = 4 b-rows

// Fine-grained fused kernel, R5 structure (prefetch-before-softmax, regs
// unpinned so the 8-deep staged prefetch survives) with HALVED CTA size to
// shrink the end-of-kernel drain tail: 4096 CTAs x 4 warps instead of
// 2048 x 8. Same 24 warps/SM steady state (6 CTAs/SM at ~80 regs).
//
// Reshape-trick index: x_sum[b,d] = sum_k nt[k,b,d] * w[k, (b&127)*128 + d];
// all b with residue r = b&127 share one 128-column softmax (smem, per CTA).
//
// nt (256 MB, single-use, 2x L2) -> __ldcs evict-first; outputs -> __stcs.
// Softmax is two-pass (running max, reload ne from L2) to stay reg-lean under
// the live prefetch; with block=128 every thread owns one softmax column.

__global__ void __launch_bounds__(128) fused_all(
    const float* __restrict__ ne,   // [K, B]
    const float* __restrict__ nt,   // [K, B, DA]
    const float* __restrict__ np,   // [DA]
    const float* __restrict__ ew,   // [DA]
    const float* __restrict__ eb,   // [1]
    const float* __restrict__ tw,   // [DA]
    const float* __restrict__ tb,   // [DA]
    float* __restrict__ out)        // [B + B*DA]
{
    const int r = blockIdx.x & 127;      // residue
    const int s = blockIdx.x >> 7;       // split in [0, SPLITS)
    const int t = threadIdx.x;
    const int warp = t >> 5;
    const int lane = t & 31;
    const int b = r + 128 * (s * 4 + warp);

    __shared__ float wsm[K][DA];         // 16 KB softmax weights for this residue

    const size_t kstride4 = (size_t)B * DA / 4;   // float4 stride between k-slices
    const float4* nt4 = reinterpret_cast<const float4*>(nt + (size_t)b * DA) + lane;
    const float4* w4  = reinterpret_cast<const float4*>(&wsm[0][0]) + lane;  // + k*32

    // ---- prefetch batch 0 (k = 0..7) BEFORE softmax: HBM busy immediately ----
    float4 a[8];
#pragma unroll
    for (int j = 0; j < 8; j++)
        a[j] = __ldcs(nt4 + (size_t)j * kstride4);

    // ---- two-pass softmax: all 128 threads, one column each (reg-lean) ----
    {
        const float* nec = ne + r * DA + t;
        float m = -1e30f;
#pragma unroll
        for (int k = 0; k < K; k++)
            m = fmaxf(m, __ldg(nec + k * B));
        float ssum = 0.0f;
#pragma unroll
        for (int k = 0; k < K; k++) {
            const float e = __expf(__ldg(nec + k * B) - m);   // L2 hit on reload
            wsm[k][t] = e;
            ssum += e;
        }
        const float inv = __frcp_rn(ssum);
#pragma unroll
        for (int k = 0; k < K; k++)
            wsm[k][t] *= inv;
    }
    __syncthreads();

    // ---- streaming accumulation: batch 0 from prefetch, then k0 = 8,16,24 ----
    float4 acc = make_float4(0.f, 0.f, 0.f, 0.f);

#pragma unroll
    for (int j = 0; j < 8; j++) {
        const float4 w = w4[j * 32];                 // conflict-free LDS.128
        acc.x = fmaf(a[j].x, w.x, acc.x);
        acc.y = fmaf(a[j].y, w.y, acc.y);
        acc.z = fmaf(a[j].z, w.z, acc.z);
        acc.w = fmaf(a[j].w, w.w, acc.w);
    }

#pragma unroll
    for (int k0 = 8; k0 < K; k0 += 8) {
#pragma unroll
        for (int j = 0; j < 8; j++)
            a[j] = __ldcs(nt4 + (size_t)(k0 + j) * kstride4);
#pragma unroll
        for (int j = 0; j < 8; j++) {
            const float4 w = w4[(k0 + j) * 32];
            acc.x = fmaf(a[j].x, w.x, acc.x);
            acc.y = fmaf(a[j].y, w.y, acc.y);
            acc.z = fmaf(a[j].z, w.z, acc.z);
            acc.w = fmaf(a[j].w, w.w, acc.w);
        }
    }

    // ---- epilogue ----
    const float4 npv = __ldg(reinterpret_cast<const float4*>(np) + lane);
    float4 x_;
    x_.x = npv.x * acc.x;
    x_.y = npv.y * acc.y;
    x_.z = npv.z * acc.z;
    x_.w = npv.w * acc.w;

    const float4 ewv = __ldg(reinterpret_cast<const float4*>(ew) + lane);
    float dot = x_.x * ewv.x + x_.y * ewv.y + x_.z * ewv.z + x_.w * ewv.w;
#pragma unroll
    for (int off = 16; off > 0; off >>= 1)
        dot += __shfl_xor_sync(0xFFFFFFFFu, dot, off);

    const float effect = __frcp_rn(1.0f + __expf(-(dot + __ldg(eb))));

    if (lane == 0) __stcs(out + b, effect);

    const float4 twv = __ldg(reinterpret_cast<const float4*>(tw) + lane);
    const float4 tbv = __ldg(reinterpret_cast<const float4*>(tb) + lane);
    float4 res;
    res.x = effect * fmaf(twv.x, x_.x, tbv.x);
    res.y = effect * fmaf(twv.y, x_.y, tbv.y);
    res.z = effect * fmaf(twv.z, x_.z, tbv.z);
    res.w = effect * fmaf(twv.w, x_.w, tbv.w);

    __stcs(reinterpret_cast<float4*>(out + B + (size_t)b * DA) + lane, res);
}

extern "C" void kernel_launch(void* const* d_in, const int* in_sizes, int n_in,
                              void* d_out, int out_size) {
    // metadata order: x, neigh_effect, neigh_transform, n_param, ew, eb, tw, tb
    const float* ne = (const float*)d_in[1];
    const float* nt = (const float*)d_in[2];
    const float* np = (const float*)d_in[3];
    const float* ew = (const float*)d_in[4];
    const float* eb = (const float*)d_in[5];
    const float* tw = (const float*)d_in[6];
    const float* tb = (const float*)d_in[7];
    float* out = (float*)d_out;

    // 128 residues x 32 splits = 4096 CTAs; 4 warps/CTA -> one b-row per warp
    fused_all<<<128 * SPLITS, 128>>>(ne, nt, np, ew, eb, tw, tb, out);
}